// round 6
// baseline (speedup 1.0000x reference)
#include <cuda_runtime.h>
#include <cstdint>

#define N_NODES 200000
#define F_IN    128
#define H_DIM   64
#define C_OUT   40
#define MAXDEG  5
#define NBUCKET 6
#define NUM_LAYERS 2
#define E_MAX   3400000

#define SCAN_ELEMS 1024
#define NUM_SCAN_BLOCKS ((N_NODES + SCAN_ELEMS - 1) / SCAN_ELEMS)   // 196

typedef unsigned long long u64;

// ---------------- scratch (__device__ globals: allocation-free rule) --------
__device__ float g_h  [(size_t)N_NODES * H_DIM];
__device__ float g_x1 [(size_t)N_NODES * H_DIM];
__device__ float g_agg[(size_t)N_NODES * H_DIM];
__device__ int   g_cnt[N_NODES];
__device__ int   g_deg[N_NODES];
__device__ int   g_rowptr[N_NODES + 1];
__device__ int   g_cursor[N_NODES];
__device__ int   g_esrc[E_MAX];
__device__ int   g_blocksums[NUM_SCAN_BLOCKS];
__device__ int   g_bcnt[NBUCKET];
__device__ int   g_bcur[NBUCKET];
__device__ int   g_nodes_sorted[N_NODES];

// ---------------- packed f32x2 helpers --------------------------------------
__device__ __forceinline__ u64 pack2(float a, float b) {
    u64 r;
    asm("mov.b64 %0, {%1, %2};" : "=l"(r) : "f"(a), "f"(b));
    return r;
}
__device__ __forceinline__ float2 unpack2(u64 v) {
    float2 r;
    asm("mov.b64 {%0, %1}, %2;" : "=f"(r.x), "=f"(r.y) : "l"(v));
    return r;
}
__device__ __forceinline__ void ffma2(u64& d, u64 a, u64 b) {
    asm("fma.rn.f32x2 %0, %1, %2, %0;" : "+l"(d) : "l"(a), "l"(b));
}

// ---------------------------------------------------------------------------
// setup
// ---------------------------------------------------------------------------
__global__ void zero_kernel() {
    int i = blockIdx.x * blockDim.x + threadIdx.x;
    if (i < N_NODES) g_cnt[i] = 0;
    if (i < NBUCKET) g_bcnt[i] = 0;
}

__global__ void count_kernel(const int* __restrict__ src, const int* __restrict__ dst,
                             int E, int vec_ok) {
    int e = (blockIdx.x * blockDim.x + threadIdx.x) * 4;
    if (vec_ok && e + 3 < E) {
        int4 s = *(const int4*)(src + e);
        int4 d = *(const int4*)(dst + e);
        if (s.x != d.x) atomicAdd(&g_cnt[d.x], 1);
        if (s.y != d.y) atomicAdd(&g_cnt[d.y], 1);
        if (s.z != d.z) atomicAdd(&g_cnt[d.z], 1);
        if (s.w != d.w) atomicAdd(&g_cnt[d.w], 1);
    } else {
        for (; e < E && e < (blockIdx.x * blockDim.x + threadIdx.x) * 4 + 4; e++) {
            int s = src[e], d = dst[e];
            if (s != d) atomicAdd(&g_cnt[d], 1);
        }
    }
}

__global__ void scan_local_kernel() {
    __shared__ int ssum[256];
    int t = threadIdx.x;
    int base = blockIdx.x * SCAN_ELEMS + t * 4;
    int c[4];
    int s = 0;
#pragma unroll
    for (int j = 0; j < 4; j++) {
        int idx = base + j;
        c[j] = (idx < N_NODES) ? g_cnt[idx] : 0;
        s += c[j];
    }
    ssum[t] = s;
    __syncthreads();
#pragma unroll
    for (int off = 1; off < 256; off <<= 1) {
        int v = (t >= off) ? ssum[t - off] : 0;
        __syncthreads();
        ssum[t] += v;
        __syncthreads();
    }
    int p = ssum[t] - s;
#pragma unroll
    for (int j = 0; j < 4; j++) {
        int idx = base + j;
        if (idx < N_NODES) g_rowptr[idx] = p;
        p += c[j];
    }
    if (t == 0) g_blocksums[blockIdx.x] = ssum[255];
}

__global__ void scan_blocksums_kernel() {
    __shared__ int sb[256];
    int t = threadIdx.x;
    int own = (t < NUM_SCAN_BLOCKS) ? g_blocksums[t] : 0;
    sb[t] = own;
    __syncthreads();
#pragma unroll
    for (int off = 1; off < 256; off <<= 1) {
        int v = (t >= off) ? sb[t - off] : 0;
        __syncthreads();
        sb[t] += v;
        __syncthreads();
    }
    if (t < NUM_SCAN_BLOCKS) g_blocksums[t] = sb[t] - own;
    if (t == 0) g_rowptr[N_NODES] = sb[255];
}

__global__ void scan_add_kernel() {
    int i = blockIdx.x * blockDim.x + threadIdx.x;
    if (i >= N_NODES) return;
    int r = g_rowptr[i] + g_blocksums[i / SCAN_ELEMS];
    g_rowptr[i] = r;
    g_cursor[i] = r;
    int dg = g_cnt[i];
    dg = dg > MAXDEG ? MAXDEG : dg;
    g_deg[i] = dg;
    atomicAdd(&g_bcnt[dg], 1);
}

__global__ void bucket_offsets_kernel() {
    int off = 0;
#pragma unroll
    for (int k = 0; k < NBUCKET; k++) { g_bcur[k] = off; off += g_bcnt[k]; }
}

__global__ void bucket_fill_kernel() {
    int i = blockIdx.x * blockDim.x + threadIdx.x;
    if (i >= N_NODES) return;
    int pos = atomicAdd(&g_bcur[g_deg[i]], 1);
    g_nodes_sorted[pos] = i;
}

__global__ void csr_fill_kernel(const int* __restrict__ src, const int* __restrict__ dst,
                                int E, int vec_ok) {
    int e = (blockIdx.x * blockDim.x + threadIdx.x) * 4;
    if (vec_ok && e + 3 < E) {
        int4 s = *(const int4*)(src + e);
        int4 d = *(const int4*)(dst + e);
        if (s.x != d.x) { int p = atomicAdd(&g_cursor[d.x], 1); if (p < E_MAX) g_esrc[p] = s.x; }
        if (s.y != d.y) { int p = atomicAdd(&g_cursor[d.y], 1); if (p < E_MAX) g_esrc[p] = s.y; }
        if (s.z != d.z) { int p = atomicAdd(&g_cursor[d.z], 1); if (p < E_MAX) g_esrc[p] = s.z; }
        if (s.w != d.w) { int p = atomicAdd(&g_cursor[d.w], 1); if (p < E_MAX) g_esrc[p] = s.w; }
    } else {
        for (; e < E && e < (blockIdx.x * blockDim.x + threadIdx.x) * 4 + 4; e++) {
            int s = src[e], d = dst[e];
            if (s != d) { int p = atomicAdd(&g_cursor[d], 1); if (p < E_MAX) g_esrc[p] = s; }
        }
    }
}

// ---------------------------------------------------------------------------
// gemm1: h = relu(x @ W1 + b1); x_first = h.  8 nodes/warp, FFMA2.
// Dyn smem: Wd[F_IN][32] float4 = (w0,w0,w1,w1) for cols (2c,2c+1); bias pairs.
// ---------------------------------------------------------------------------
__global__ void gemm1_kernel(const float* __restrict__ x,
                             const float* __restrict__ W1,
                             const float* __restrict__ b1) {
    extern __shared__ unsigned char dyn1[];
    float4* Wd = (float4*)dyn1;                         // [F_IN][32]
    float2* bp = (float2*)(dyn1 + F_IN * 32 * 16);      // [32]
    int tid = threadIdx.x;
    for (int i = tid; i < F_IN * 32; i += blockDim.x) {
        int k = i >> 5, c = i & 31;
        float w0 = W1[k * H_DIM + 2 * c], w1 = W1[k * H_DIM + 2 * c + 1];
        Wd[i] = make_float4(w0, w0, w1, w1);
    }
    if (tid < 32) bp[tid] = make_float2(b1[2 * tid], b1[2 * tid + 1]);
    __syncthreads();

    int lane = tid & 31;
    int warp = (blockIdx.x * blockDim.x + tid) >> 5;
    int nwarps = (gridDim.x * blockDim.x) >> 5;
    const int NG = N_NODES / 8;                          // 25000

    for (int g = warp; g < NG; g += nwarps) {
        int n0 = 8 * g;
        float4 xr[8];
#pragma unroll
        for (int j = 0; j < 8; j++)
            xr[j] = *(const float4*)(x + (size_t)(n0 + j) * F_IN + lane * 4);
        u64 ox[4] = {0, 0, 0, 0}, oy[4] = {0, 0, 0, 0};
        const ulonglong2* Wrow = (const ulonglong2*)Wd + lane;
#pragma unroll 32
        for (int k = 0; k < F_IN; k++) {
            ulonglong2 w = Wrow[k * 32];
            float av[8];
#pragma unroll
            for (int j = 0; j < 8; j++) {
                float mine = ((k & 3) == 0) ? xr[j].x : ((k & 3) == 1) ? xr[j].y
                           : ((k & 3) == 2) ? xr[j].z : xr[j].w;
                av[j] = __shfl_sync(0xffffffffu, mine, k >> 2);
            }
#pragma unroll
            for (int p = 0; p < 4; p++) {
                u64 a2 = pack2(av[2 * p], av[2 * p + 1]);
                ffma2(ox[p], a2, w.x);
                ffma2(oy[p], a2, w.y);
            }
        }
        float2 b = bp[lane];
#pragma unroll
        for (int p = 0; p < 4; p++) {
            float2 vx = unpack2(ox[p]);   // (node 2p, node 2p+1) @ col 2*lane
            float2 vy = unpack2(oy[p]);   // (node 2p, node 2p+1) @ col 2*lane+1
            float2 r0 = make_float2(fmaxf(vx.x + b.x, 0.f), fmaxf(vy.x + b.y, 0.f));
            float2 r1 = make_float2(fmaxf(vx.y + b.x, 0.f), fmaxf(vy.y + b.y, 0.f));
            size_t b0 = (size_t)(n0 + 2 * p) * H_DIM + 2 * lane;
            size_t b1o = (size_t)(n0 + 2 * p + 1) * H_DIM + 2 * lane;
            *(float2*)(g_h  + b0)  = r0;  *(float2*)(g_x1 + b0)  = r0;
            *(float2*)(g_h  + b1o) = r1;  *(float2*)(g_x1 + b1o) = r1;
        }
    }
}

// ---------------------------------------------------------------------------
// agg: agg[n] = h[n] + sum CSR row.  Warp per node.
// ---------------------------------------------------------------------------
__global__ void agg_kernel() {
    int lane = threadIdx.x & 31;
    int node = (blockIdx.x * blockDim.x + threadIdx.x) >> 5;
    if (node >= N_NODES) return;
    int rs = g_rowptr[node], re = g_rowptr[node + 1];
    size_t col = 2 * lane;
    float2 acc = *(const float2*)(g_h + (size_t)node * H_DIM + col);
    int e = rs;
    for (; e + 4 <= re; e += 4) {
        int s0 = __ldg(g_esrc + e + 0);
        int s1 = __ldg(g_esrc + e + 1);
        int s2 = __ldg(g_esrc + e + 2);
        int s3 = __ldg(g_esrc + e + 3);
        float2 v0 = *(const float2*)(g_h + (size_t)s0 * H_DIM + col);
        float2 v1 = *(const float2*)(g_h + (size_t)s1 * H_DIM + col);
        float2 v2 = *(const float2*)(g_h + (size_t)s2 * H_DIM + col);
        float2 v3 = *(const float2*)(g_h + (size_t)s3 * H_DIM + col);
        acc.x += (v0.x + v1.x) + (v2.x + v3.x);
        acc.y += (v0.y + v1.y) + (v2.y + v3.y);
    }
    for (; e < re; e++) {
        int s0 = __ldg(g_esrc + e);
        float2 v = *(const float2*)(g_h + (size_t)s0 * H_DIM + col);
        acc.x += v.x; acc.y += v.y;
    }
    *(float2*)(g_agg + (size_t)node * H_DIM + col) = acc;
}

// ---------------------------------------------------------------------------
// conv: h = agg @ relW[l][deg] + relb[l][deg] + fuse*x_first.
// 8 same-degree nodes/warp via g_nodes_sorted, FFMA2, dup-weights in dyn smem.
// ---------------------------------------------------------------------------
__global__ void conv_kernel(const float* __restrict__ relW,
                            const float* __restrict__ relb,
                            const float* __restrict__ fuse,
                            int layer) {
    extern __shared__ unsigned char dync[];
    float4* Wd = (float4*)dync;                                   // [NB][H][32]
    float2* bp = (float2*)(dync + NBUCKET * H_DIM * 32 * 16);     // [NB][32]

    const float* W = relW + (size_t)layer * NBUCKET * H_DIM * H_DIM;
    const float* B = relb + (size_t)layer * NBUCKET * H_DIM;

    int tid = threadIdx.x;
    for (int i = tid; i < NBUCKET * H_DIM * 32; i += blockDim.x) {
        int k = i / (H_DIM * 32);
        int r = i - k * (H_DIM * 32);
        int d = r >> 5, c = r & 31;
        const float* Wk = W + ((size_t)k * H_DIM + d) * H_DIM;
        float w0 = Wk[2 * c], w1 = Wk[2 * c + 1];
        Wd[i] = make_float4(w0, w0, w1, w1);
    }
    for (int i = tid; i < NBUCKET * 32; i += blockDim.x) {
        int k = i >> 5, c = i & 31;
        bp[i] = make_float2(B[k * H_DIM + 2 * c], B[k * H_DIM + 2 * c + 1]);
    }
    __syncthreads();

    float fu = fuse[layer];
    int lane = tid & 31;
    int warp = (blockIdx.x * blockDim.x + tid) >> 5;
    int nwarps = (gridDim.x * blockDim.x) >> 5;
    const int NG = N_NODES / 8;

    for (int g = warp; g < NG; g += nwarps) {
        int nid[8], dg[8];
#pragma unroll
        for (int j = 0; j < 8; j++) {
            nid[j] = g_nodes_sorted[8 * g + j];
            dg[j]  = g_deg[nid[j]];
        }
        bool same = true;
#pragma unroll
        for (int j = 1; j < 8; j++) same = same && (dg[j] == dg[0]);

        if (same) {
            float2 a[8];
#pragma unroll
            for (int j = 0; j < 8; j++)
                a[j] = *(const float2*)(g_agg + (size_t)nid[j] * H_DIM + 2 * lane);
            u64 ox[4] = {0, 0, 0, 0}, oy[4] = {0, 0, 0, 0};
            const ulonglong2* Wrow = (const ulonglong2*)(Wd + (size_t)dg[0] * H_DIM * 32) + lane;
#pragma unroll 32
            for (int d = 0; d < H_DIM; d++) {
                ulonglong2 w = Wrow[d * 32];
                float av[8];
#pragma unroll
                for (int j = 0; j < 8; j++)
                    av[j] = __shfl_sync(0xffffffffu, (d & 1) ? a[j].y : a[j].x, d >> 1);
#pragma unroll
                for (int p = 0; p < 4; p++) {
                    u64 a2 = pack2(av[2 * p], av[2 * p + 1]);
                    ffma2(ox[p], a2, w.x);
                    ffma2(oy[p], a2, w.y);
                }
            }
            float2 b = bp[dg[0] * 32 + lane];
#pragma unroll
            for (int p = 0; p < 4; p++) {
                float2 vx = unpack2(ox[p]);
                float2 vy = unpack2(oy[p]);
                size_t b0 = (size_t)nid[2 * p] * H_DIM + 2 * lane;
                size_t b1o = (size_t)nid[2 * p + 1] * H_DIM + 2 * lane;
                float2 x0 = *(const float2*)(g_x1 + b0);
                float2 x1v = *(const float2*)(g_x1 + b1o);
                *(float2*)(g_h + b0) =
                    make_float2(vx.x + b.x + fu * x0.x,  vy.x + b.y + fu * x0.y);
                *(float2*)(g_h + b1o) =
                    make_float2(vx.y + b.x + fu * x1v.x, vy.y + b.y + fu * x1v.y);
            }
        } else {
            // bucket-boundary group (rare): per-node path
            for (int j = 0; j < 8; j++) {
                const float4* Wk = Wd + (size_t)dg[j] * H_DIM * 32;
                float2 a = *(const float2*)(g_agg + (size_t)nid[j] * H_DIM + 2 * lane);
                float o0 = 0.f, o1 = 0.f;
#pragma unroll
                for (int d = 0; d < H_DIM; d++) {
                    float av = __shfl_sync(0xffffffffu, (d & 1) ? a.y : a.x, d >> 1);
                    float4 w = Wk[d * 32 + lane];
                    o0 = fmaf(av, w.x, o0);
                    o1 = fmaf(av, w.z, o1);
                }
                float2 b = bp[dg[j] * 32 + lane];
                size_t base = (size_t)nid[j] * H_DIM + 2 * lane;
                float2 x1v = *(const float2*)(g_x1 + base);
                *(float2*)(g_h + base) =
                    make_float2(o0 + b.x + fu * x1v.x, o1 + b.y + fu * x1v.y);
            }
        }
    }
}

// ---------------------------------------------------------------------------
// out = log_softmax(h @ Wout + bout).  8 nodes/warp, FFMA2.
// Lane l owns cols (2l, 2l+1), valid for l < 20.
// ---------------------------------------------------------------------------
__global__ void out_kernel(const float* __restrict__ Wout,
                           const float* __restrict__ bout,
                           float* __restrict__ out) {
    __shared__ float4 Wd[H_DIM][32];
    __shared__ float2 bp[32];
    int tid = threadIdx.x;
    for (int i = tid; i < H_DIM * 32; i += blockDim.x) {
        int d = i >> 5, c = i & 31;
        float w0 = 0.f, w1 = 0.f;
        if (c < C_OUT / 2) { w0 = Wout[d * C_OUT + 2 * c]; w1 = Wout[d * C_OUT + 2 * c + 1]; }
        Wd[d][c] = make_float4(w0, w0, w1, w1);
    }
    if (tid < 32)
        bp[tid] = (tid < C_OUT / 2) ? make_float2(bout[2 * tid], bout[2 * tid + 1])
                                    : make_float2(0.f, 0.f);
    __syncthreads();

    int lane = tid & 31;
    int warp = (blockIdx.x * blockDim.x + tid) >> 5;
    int nwarps = (gridDim.x * blockDim.x) >> 5;
    const int NG = N_NODES / 8;
    bool valid = (lane < C_OUT / 2);

    for (int g = warp; g < NG; g += nwarps) {
        int n0 = 8 * g;
        float2 hr[8];
#pragma unroll
        for (int j = 0; j < 8; j++)
            hr[j] = *(const float2*)(g_h + (size_t)(n0 + j) * H_DIM + 2 * lane);
        u64 ox[4] = {0, 0, 0, 0}, oy[4] = {0, 0, 0, 0};
        const ulonglong2* Wrow = (const ulonglong2*)&Wd[0][0] + lane;
#pragma unroll 32
        for (int d = 0; d < H_DIM; d++) {
            ulonglong2 w = Wrow[d * 32];
            float av[8];
#pragma unroll
            for (int j = 0; j < 8; j++)
                av[j] = __shfl_sync(0xffffffffu, (d & 1) ? hr[j].y : hr[j].x, d >> 1);
#pragma unroll
            for (int p = 0; p < 4; p++) {
                u64 a2 = pack2(av[2 * p], av[2 * p + 1]);
                ffma2(ox[p], a2, w.x);
                ffma2(oy[p], a2, w.y);
            }
        }
        float2 b = bp[lane];
#pragma unroll
        for (int j = 0; j < 8; j++) {
            int p = j >> 1;
            float2 vx = unpack2(ox[p]);
            float2 vy = unpack2(oy[p]);
            float a0 = ((j & 1) ? vx.y : vx.x) + b.x;
            float a1 = ((j & 1) ? vy.y : vy.x) + b.y;
            float m = valid ? fmaxf(a0, a1) : -3.4e38f;
#pragma unroll
            for (int off = 16; off; off >>= 1)
                m = fmaxf(m, __shfl_xor_sync(0xffffffffu, m, off));
            float s = valid ? (expf(a0 - m) + expf(a1 - m)) : 0.f;
#pragma unroll
            for (int off = 16; off; off >>= 1)
                s += __shfl_xor_sync(0xffffffffu, s, off);
            float lse = logf(s);
            if (valid)
                *(float2*)(out + (size_t)(n0 + j) * C_OUT + 2 * lane) =
                    make_float2(a0 - m - lse, a1 - m - lse);
        }
    }
}

// ---------------------------------------------------------------------------
// launch
// ---------------------------------------------------------------------------
extern "C" void kernel_launch(void* const* d_in, const int* in_sizes, int n_in,
                              void* d_out, int out_size) {
    const float* x    = (const float*)d_in[0];
    const int*   edge = (const int*)  d_in[1];
    const float* W1   = (const float*)d_in[2];
    const float* b1   = (const float*)d_in[3];
    const float* relW = (const float*)d_in[4];
    const float* relb = (const float*)d_in[5];
    const float* Wout = (const float*)d_in[6];
    const float* bout = (const float*)d_in[7];
    const float* fuse = (const float*)d_in[8];
    float*       out  = (float*)d_out;
    int E = in_sizes[1] / 2;
    const int* srcp = edge;
    const int* dstp = edge + E;
    int vec_ok = ((E & 3) == 0) ? 1 : 0;   // int4 alignment of dstp + tail-free body

    const int gemm1_smem = F_IN * 32 * 16 + 32 * 8;                               // 65,792 B
    const int conv_smem  = NBUCKET * H_DIM * 32 * 16 + NBUCKET * 32 * 8;          // 198,144 B
    cudaFuncSetAttribute(gemm1_kernel, cudaFuncAttributeMaxDynamicSharedMemorySize, gemm1_smem);
    cudaFuncSetAttribute(conv_kernel,  cudaFuncAttributeMaxDynamicSharedMemorySize, conv_smem);

    // ---- fork: gemm1 (depends only on x,W1,b1) overlaps CSR setup ----
    cudaStream_t s1 = 0;
    cudaEvent_t evA = 0, evB = 0;
    cudaStreamCreateWithFlags(&s1, cudaStreamNonBlocking);
    cudaEventCreateWithFlags(&evA, cudaEventDisableTiming);
    cudaEventCreateWithFlags(&evB, cudaEventDisableTiming);

    cudaEventRecord(evA, (cudaStream_t)0);
    cudaStreamWaitEvent(s1, evA, 0);
    gemm1_kernel<<<296, 512, gemm1_smem, s1>>>(x, W1, b1);
    cudaEventRecord(evB, s1);

    // ---- setup on main stream: degree counts, CSR, degree buckets ----
    zero_kernel<<<(N_NODES + 255) / 256, 256>>>();
    count_kernel<<<((E + 3) / 4 + 255) / 256, 256>>>(srcp, dstp, E, vec_ok);
    scan_local_kernel<<<NUM_SCAN_BLOCKS, 256>>>();
    scan_blocksums_kernel<<<1, 256>>>();
    scan_add_kernel<<<(N_NODES + 255) / 256, 256>>>();
    bucket_offsets_kernel<<<1, 1>>>();
    bucket_fill_kernel<<<(N_NODES + 255) / 256, 256>>>();
    csr_fill_kernel<<<((E + 3) / 4 + 255) / 256, 256>>>(srcp, dstp, E, vec_ok);

    // ---- join, then network ----
    cudaStreamWaitEvent((cudaStream_t)0, evB, 0);
    for (int l = 0; l < NUM_LAYERS; l++) {
        agg_kernel<<<(N_NODES * 32 + 255) / 256, 256>>>();
        conv_kernel<<<148, 512, conv_smem>>>(relW, relb, fuse, l);
    }
    out_kernel<<<592, 256>>>(Wout, bout, out);
    // s1/evA/evB intentionally not destroyed here: kernel_launch is invoked only
    // a handful of times (correctness + capture), and destroying a forked stream
    // mid-capture is illegal. No device memory is involved.
}